// round 14
// baseline (speedup 1.0000x reference)
#include <cuda_runtime.h>

#define HN 4096

constexpr int TH = 64;                     // output rows per warp-tile
constexpr int OUTW = 56;                   // output cols per warp strip (float2 lanes)
constexpr int NSTRIPS = 74;                // 74*56 = 4144 >= 4096
constexpr int WPB = 4;
constexpr int NTILES = NSTRIPS * (HN / TH);   // 4736
constexpr int NBLK = NTILES / WPB;            // 1184 = 8 * 148
constexpr int N_INT = 72 * 62;                // 4464 interior tiles
constexpr int N_EDGE = NTILES - N_INT;        // 272, spread 1-per-block

__device__ double g_accs[8 * 16];   // 8 slots, 128B apart; reset by last block
__device__ unsigned g_done;

static __device__ __forceinline__ float2 ld2p(const float* p, bool v) {
    float2 r = make_float2(0.f, 0.f);
    if (v) r = *reinterpret_cast<const float2*>(p);
    return r;
}

// 4-tap window over cols for a float2 lane (cols 2l,2l+1):
// G.x = leftY + v.x + v.y + rightX ;  G.y = v.x + v.y + rightX + rightY
static __device__ __forceinline__ float2 hwin2(float2 v, float lY, float rX, float rY) {
    float s = v.x + v.y;
    float t = s + rX;
    float2 g;
    g.x = lY + t;
    g.y = t + rY;
    return g;
}

static __device__ __forceinline__ float maskf(float x, unsigned m) {
    return __uint_as_float(__float_as_uint(x) & m);
}

// pack two floats as bf16x2 (a -> lo half, b -> hi half)
static __device__ __forceinline__ unsigned bpack(float a, float b) {
    unsigned r;
    asm("cvt.rn.bf16x2.f32 %0, %1, %2;" : "=r"(r) : "f"(b), "f"(a));
    return r;
}
static __device__ __forceinline__ float bf_lo(unsigned p) {
    return __uint_as_float(p << 16);
}
static __device__ __forceinline__ float bf_hi(unsigned p) {
    return __uint_as_float(p & 0xffff0000u);
}

template<bool EDGE>
static __device__ __forceinline__ float tile_compute(
    const float* __restrict__ X, const float* __restrict__ Y,
    int strip, int tyt, int lane)
{
    const int ty0 = tyt * TH;
    const long col0 = (long)strip * OUTW - 4 + 2 * lane;
    const bool ld_ok = EDGE ? ((col0 >= 0) && (col0 + 1 < HN)) : true;
    const unsigned mCb = EDGE ? ((lane >= 1 && lane <= 30 && ld_ok) ? ~0u : 0u) : ~0u;
    const float mO = ((lane >= 2 && lane <= 29) && ld_ok) ? 1.f : 0.f;
    const float mOn = -mO;
    const int i0 = ty0 - 8;   // multiple of 4

    // pX/pY track the prefetch row (i+6) of the current step
    const float* pX = X + col0 + (long)(i0 + 6) * HN;
    const float* pY = Y + col0 + (long)(i0 + 6) * HN;

    // 2-deep prefetch, phase-rotated
    float2 xs[2], ys[2];
    {
        bool v4 = EDGE ? (ld_ok && (unsigned)(i0 + 4) < HN) : true;
        bool v5 = EDGE ? (ld_ok && (unsigned)(i0 + 5) < HN) : true;
        xs[0] = ld2p(pX - 2 * HN, v4); ys[0] = ld2p(pY - 2 * HN, v4);
        xs[1] = ld2p(pX - 1 * HN, v5); ys[1] = ld2p(pY - 1 * HN, v5);
    }

    // rings: raw rows (slot = row index & 3) and centered rows
    float2 rx[4], ry[4], rc1[4], rc2[4];
    float2 Vx, Vy, Vi, Vj, Vc;
    {
        float2 z = make_float2(0.f, 0.f);
#pragma unroll
        for (int s = 0; s < 4; ++s) { rx[s] = z; ry[s] = z; rc1[s] = z; rc2[s] = z; }
        Vx = Vy = Vi = Vj = Vc = z;
    }

    float acc = 0.f;   // accumulates -L over valid output pixels

#define STEP(T, S, DO_OUT) do {                                                  \
    const int i = i0 + (T) + (S); (void)i;                                       \
    const int p_ = (S) & 1;                                                      \
    float2 xc = xs[p_], yc = ys[p_];                                             \
    {   bool v6 = EDGE ? (ld_ok && (unsigned)(i + 6) < HN) : true;               \
        xs[p_] = ld2p(pX, v6); ys[p_] = ld2p(pY, v6);                            \
        pX += HN; pY += HN; }                                                    \
    /* rolling vertical raw sums: +row(i+4), -row(i) (ring slot S) */            \
    {   float2 xo = rx[(S)]; rx[(S)] = xc;                                       \
        float2 yo = ry[(S)]; ry[(S)] = yc;                                       \
        Vx.x += xc.x - xo.x; Vx.y += xc.y - xo.y;                                \
        Vy.x += yc.x - yo.x; Vy.y += yc.y - yo.y; }                              \
    float2 x2 = rx[((S) + 2) & 3], y2 = ry[((S) + 2) & 3];  /* row i+2 */        \
    /* packed boundary shuffles: (Vx,Vy) in one bf16x2 payload */                \
    unsigned ph_ = bpack(Vx.y, Vy.y);                                            \
    unsigned pl_ = bpack(Vx.x, Vy.x);                                            \
    unsigned uY_ = __shfl_up_sync(0xffffffffu, ph_, 1);                          \
    unsigned dX_ = __shfl_down_sync(0xffffffffu, pl_, 1);                        \
    unsigned dY_ = __shfl_down_sync(0xffffffffu, ph_, 1);                        \
    float2 mx = hwin2(Vx, bf_lo(uY_), bf_lo(dX_), bf_lo(dY_));  /* 16*mu */      \
    float2 my = hwin2(Vy, bf_hi(uY_), bf_hi(dX_), bf_hi(dY_));                   \
    unsigned rmask = EDGE ? (((unsigned)(i + 2) < HN) ? mCb : 0u) : ~0u;         \
    float2 c1, c2;                                                               \
    c1.x = maskf(fmaf(mx.x, -0.0625f, x2.x), rmask);                             \
    c1.y = maskf(fmaf(mx.y, -0.0625f, x2.y), rmask);                             \
    c2.x = maskf(fmaf(my.x, -0.0625f, y2.x), rmask);                             \
    c2.y = maskf(fmaf(my.y, -0.0625f, y2.y), rmask);                             \
    /* rolling vertical sig sums over product rows i-1..i+2; ring stores c */    \
    {   const int sl = ((S) + 2) & 3;                                            \
        float2 o1 = rc1[sl], o2 = rc2[sl];                                       \
        rc1[sl] = c1; rc2[sl] = c2;                                              \
        Vi.x = fmaf(c1.x, c1.x, fmaf(o1.x, -o1.x, Vi.x));                        \
        Vi.y = fmaf(c1.y, c1.y, fmaf(o1.y, -o1.y, Vi.y));                        \
        Vj.x = fmaf(c2.x, c2.x, fmaf(o2.x, -o2.x, Vj.x));                        \
        Vj.y = fmaf(c2.y, c2.y, fmaf(o2.y, -o2.y, Vj.y));                        \
        Vc.x = fmaf(c1.x, c2.x, fmaf(o1.x, -o2.x, Vc.x));                        \
        Vc.y = fmaf(c1.y, c2.y, fmaf(o1.y, -o2.y, Vc.y));                        \
    }                                                                            \
    if (DO_OUT) {  /* compile-time: output row i */                              \
        unsigned qh_ = bpack(Vi.y, Vj.y);                                        \
        unsigned ql_ = bpack(Vi.x, Vj.x);                                        \
        unsigned tU_ = __shfl_up_sync(0xffffffffu, qh_, 1);                      \
        unsigned tX_ = __shfl_down_sync(0xffffffffu, ql_, 1);                    \
        unsigned tY_ = __shfl_down_sync(0xffffffffu, qh_, 1);                    \
        float cu_ = __shfl_up_sync(0xffffffffu, Vc.y, 1);                        \
        float cx_ = __shfl_down_sync(0xffffffffu, Vc.x, 1);                      \
        float cy_ = __shfl_down_sync(0xffffffffu, Vc.y, 1);                      \
        float2 sii = hwin2(Vi, bf_lo(tU_), bf_lo(tX_), bf_lo(tY_));              \
        float2 sjj = hwin2(Vj, bf_hi(tU_), bf_hi(tX_), bf_hi(tY_));              \
        float2 sij = hwin2(Vc, cu_, cx_, cy_);                                   \
        { float a = fmaxf(sii.x, 1e-20f), b = fmaxf(sjj.x, 1e-20f);              \
          float L = sij.x * rsqrtf(a * b);                                       \
          acc = fmaf(L, mOn, acc); }                                             \
        { float a = fmaxf(sii.y, 1e-20f), b = fmaxf(sjj.y, 1e-20f);              \
          float L = sij.y * rsqrtf(a * b);                                       \
          acc = fmaf(L, mOn, acc); }                                             \
    }                                                                            \
} while (0)

    // ---- warmup: 8 steps, no output, no per-step branch ----
    STEP(0, 0, false); STEP(0, 1, false); STEP(0, 2, false); STEP(0, 3, false);
    STEP(4, 0, false); STEP(4, 1, false); STEP(4, 2, false); STEP(4, 3, false);

    // ---- steady state: 64 steps, unconditional output ----
#pragma unroll 1
    for (int T = 8; T < TH + 8; T += 4) {
        STEP(T, 0, true);
        STEP(T, 1, true);
        STEP(T, 2, true);
        STEP(T, 3, true);
    }
#undef STEP

    // +1 per valid output pixel (2 cols * TH rows), plus accumulated (-L)
    return fmaf((float)(TH * 2), mO, acc);
}

__global__ void __launch_bounds__(WPB * 32, 6)
xcorr_kernel(const float* __restrict__ X, const float* __restrict__ Y,
             float* __restrict__ out) {
    const int lane = threadIdx.x & 31;
    const int warp = threadIdx.x >> 5;
    const int b = blockIdx.x;

    float tot;
    if (warp == 3 && b < N_EDGE) {
        // one edge tile per early block -> edge work spread across SMs
        const int e = b;                      // 0..271
        int strip, band;
        if (e < 74)       { strip = e;        band = 0; }
        else if (e < 148) { strip = e - 74;   band = 63; }
        else { int e2 = e - 148; strip = (e2 & 1) ? (NSTRIPS - 1) : 0; band = 1 + (e2 >> 1); }
        tot = tile_compute<true>(X, Y, strip, band, lane);
    } else {
        // interior tiles: strips 1..72, bands 1..62 (4464 total)
        const int idx = (b < N_EDGE) ? (3 * b + warp) : (4 * b - N_EDGE + warp);
        const int strip = 1 + idx % 72;
        const int band = 1 + idx / 72;
        tot = tile_compute<false>(X, Y, strip, band, lane);
    }

#pragma unroll
    for (int o = 16; o; o >>= 1) tot += __shfl_xor_sync(0xffffffffu, tot, o);

    __shared__ float wsum[WPB];
    if (lane == 0) wsum[warp] = tot;
    __syncthreads();
    if (threadIdx.x == 0) {
        float s = wsum[0] + wsum[1] + wsum[2] + wsum[3];
        atomicAdd(&g_accs[(blockIdx.x & 7) * 16], (double)s);
        __threadfence();
        unsigned done = atomicAdd(&g_done, 1u);
        if (done == (unsigned)(NBLK - 1)) {   // last block finalizes
            double m = 0.0;
#pragma unroll
            for (int k = 0; k < 8; ++k)
                m += atomicAdd(&g_accs[k * 16], 0.0);   // coherent read
            m *= (1.0 / ((double)HN * (double)HN));
            out[0] = (float)m;
            out[1] = (float)m;
#pragma unroll
            for (int k = 0; k < 8; ++k) g_accs[k * 16] = 0.0;  // reset for replay
            g_done = 0u;
        }
    }
}

extern "C" void kernel_launch(void* const* d_in, const int* in_sizes, int n_in,
                              void* d_out, int out_size) {
    const float* X = (const float*)d_in[0];   // outputs
    const float* Y = (const float*)d_in[1];   // labels
    xcorr_kernel<<<NBLK, WPB * 32>>>(X, Y, (float*)d_out);
}